// round 1
// baseline (speedup 1.0000x reference)
#include <cuda_runtime.h>

// Shapes fixed by the problem's setup_inputs().
#define B_  8
#define H_  16
#define NT_ 512
#define NV_ 576

#define EPS_MIN 1e-8f
#define EPS_MAX 1.0f

// Per-layer diagonal accumulators (atomic float adds). Zeroed each launch.
__device__ float g_tdiag[2 * B_ * NT_];   // 8192 floats
__device__ float g_vdiag[2 * B_ * NV_];   // 9216 floats

__global__ void zero_scratch_kernel() {
    int idx = blockIdx.x * blockDim.x + threadIdx.x;
    if (idx < 2 * B_ * NT_) g_tdiag[idx] = 0.0f;
    if (idx < 2 * B_ * NV_) g_vdiag[idx] = 0.0f;
}

// One block = 32x32 tile of the (i in NT, j in NV) grid for one (layer, b).
// Computes prod[i][j] = (sum_h at[b,h,i,j]) * (sum_h av[b,h,j,i]) and
// accumulates row sums into g_tdiag and column sums into g_vdiag.
__global__ __launch_bounds__(1024, 1)
void diag_kernel(const float* __restrict__ at0, const float* __restrict__ av0,
                 const float* __restrict__ at1, const float* __restrict__ av1) {
    __shared__ float sh[32][33];   // padded: stride-33 transpose reads are conflict-free

    const int tx = threadIdx.x;    // lane
    const int ty = threadIdx.y;    // warp id within block
    const int z  = blockIdx.z;
    const int layer = z >> 3;
    const int b     = z & 7;

    const float* __restrict__ at = layer ? at1 : at0;
    const float* __restrict__ av = layer ? av1 : av0;

    const int i0 = blockIdx.y * 32;
    const int j0 = blockIdx.x * 32;

    // attn_t load: thread (ty,tx) -> element (i0+ty, j0+tx); tx contiguous -> coalesced
    // attn_v load: thread (ty,tx) -> element (j0+ty, i0+tx); tx contiguous -> coalesced
    const int i  = i0 + ty;
    const int j  = j0 + tx;
    const int jv = j0 + ty;
    const int iv = i0 + tx;

    const float* pt = at + ((size_t)b * H_ * NT_ + i)  * NV_ + j;
    const float* pv = av + ((size_t)b * H_ * NV_ + jv) * NT_ + iv;

    float st = 0.0f, sv = 0.0f;
#pragma unroll 4
    for (int h = 0; h < H_; ++h) {
        st += pt[(size_t)h * NT_ * NV_];
        sv += pv[(size_t)h * NV_ * NT_];
    }

    // Transpose sv tile through shared: thread (ty,tx) needs P_v-sum at (j0+tx, i0+ty).
    sh[ty][tx] = sv;
    __syncthreads();
    const float prod = st * sh[tx][ty];

    // Row sums (over j, i.e. over lanes tx) -> text_diag[b, i0+ty]
    float rs = prod;
#pragma unroll
    for (int o = 16; o > 0; o >>= 1) rs += __shfl_xor_sync(0xffffffffu, rs, o);
    if (tx == 0)
        atomicAdd(&g_tdiag[layer * (B_ * NT_) + b * NT_ + i0 + ty], rs);

    // Column sums: transpose prod through shared, then lane-reduce.
    __syncthreads();
    sh[ty][tx] = prod;
    __syncthreads();
    float cs = sh[tx][ty];         // = prod(row tx, col ty)
#pragma unroll
    for (int o = 16; o > 0; o >>= 1) cs += __shfl_xor_sync(0xffffffffu, cs, o);
    if (tx == 0)
        atomicAdd(&g_vdiag[layer * (B_ * NV_) + b * NV_ + j0 + ty], cs);
}

// Single-block reduction to the scalar loss.
__global__ __launch_bounds__(1024, 1)
void finalize_kernel(float* __restrict__ out) {
    __shared__ float red_t[32];
    __shared__ float red_v[32];
    const int tid = threadIdx.x;
    const float inv_h2 = 1.0f / (float)(H_ * H_);  // sums -> products of means

    float st = 0.0f, sv = 0.0f;
    for (int idx = tid; idx < 2 * B_ * NT_; idx += 1024) {
        float d = g_tdiag[idx] * inv_h2;
        d = fminf(fmaxf(d, EPS_MIN), EPS_MAX);
        st -= logf(d);
    }
    for (int idx = tid; idx < 2 * B_ * NV_; idx += 1024) {
        float d = g_vdiag[idx] * inv_h2;
        d = fminf(fmaxf(d, EPS_MIN), EPS_MAX);
        sv -= logf(d);
    }

#pragma unroll
    for (int o = 16; o > 0; o >>= 1) {
        st += __shfl_xor_sync(0xffffffffu, st, o);
        sv += __shfl_xor_sync(0xffffffffu, sv, o);
    }
    const int w = tid >> 5, l = tid & 31;
    if (l == 0) { red_t[w] = st; red_v[w] = sv; }
    __syncthreads();
    if (w == 0) {
        st = red_t[l];
        sv = red_v[l];
#pragma unroll
        for (int o = 16; o > 0; o >>= 1) {
            st += __shfl_xor_sync(0xffffffffu, st, o);
            sv += __shfl_xor_sync(0xffffffffu, sv, o);
        }
        if (l == 0) {
            // total = 0.25 * ((lt0+lt1) + (lv0+lv1))
            // lt0+lt1 = st / (B*NT), lv0+lv1 = sv / (B*NV)
            float loss = 0.25f * (st / (float)(B_ * NT_) + sv / (float)(B_ * NV_));
            out[0] = loss;
        }
    }
}

extern "C" void kernel_launch(void* const* d_in, const int* in_sizes, int n_in,
                              void* d_out, int out_size) {
    const float* at0 = (const float*)d_in[0];
    const float* av0 = (const float*)d_in[1];
    const float* at1 = (const float*)d_in[2];
    const float* av1 = (const float*)d_in[3];

    // 1) zero the atomic scratch (9216 max elems -> 36 blocks of 256)
    zero_scratch_kernel<<<36, 256>>>();

    // 2) fused head-mean + diagonal row/col sums
    //    grid: x = NV/32 = 18 j-tiles, y = NT/32 = 16 i-tiles, z = layer*8 + b = 16
    dim3 grid(NV_ / 32, NT_ / 32, 2 * B_);
    dim3 block(32, 32, 1);
    diag_kernel<<<grid, block>>>(at0, av0, at1, av1);

    // 3) scalar finalize
    finalize_kernel<<<1, 1024>>>((float*)d_out);
}

// round 2
// speedup vs baseline: 1.1263x; 1.1263x over previous
#include <cuda_runtime.h>

// Shapes fixed by the problem's setup_inputs().
#define B_  8
#define H_  16
#define NT_ 512
#define NV_ 576

#define EPS_MIN 1e-8f
#define EPS_MAX 1.0f

// Per-layer diagonal accumulators (atomic float adds).
// Zero-initialized at module load; finalize_kernel re-zeroes them after each
// use, so every kernel_launch call starts from zeros (deterministic).
__device__ float g_tdiag[2 * B_ * NT_];   // 8192 floats
__device__ float g_vdiag[2 * B_ * NV_];   // 9216 floats

// One block (256 threads) = 32(i) x 32(j) tile for one (layer, b).
//   thread t: p = t & 7 (float4 slot), q = t >> 3 (row index 0..31)
//   attn_t: element (i = i0+q, j = j0+4p..+3)  -> float4 along j (contiguous)
//   attn_v: element (j = j0+q, i = i0+4p..+3)  -> float4 along i (contiguous)
// prod[i][j] = P_t_sum[i][j] * P_v_sum[j][i]; row sums -> g_tdiag,
// column sums -> g_vdiag.
__global__ __launch_bounds__(256)
void diag_kernel(const float* __restrict__ at0, const float* __restrict__ av0,
                 const float* __restrict__ at1, const float* __restrict__ av1) {
    __shared__ float shV[32][33];   // P_v sums, stride-33 -> conflict-free transpose
    __shared__ float shP[32][33];   // prod tile for column reduction

    const int t = threadIdx.x;
    const int p = t & 7;            // float4 slot within row
    const int q = t >> 3;           // row (i for attn_t, j for attn_v)

    const int z     = blockIdx.z;
    const int layer = z >> 3;
    const int b     = z & 7;
    const int i0    = blockIdx.y * 32;
    const int j0    = blockIdx.x * 32;

    const float* __restrict__ at = layer ? at1 : at0;
    const float* __restrict__ av = layer ? av1 : av0;

    // Base pointers at h = 0; head stride in float4 units.
    const size_t hstride4 = (size_t)NT_ * NV_ / 4;   // 73728
    const float4* __restrict__ pt = (const float4*)(
        at + (((size_t)b * H_) * NT_ + (i0 + q)) * NV_ + (j0 + 4 * p));
    const float4* __restrict__ pv = (const float4*)(
        av + (((size_t)b * H_) * NV_ + (j0 + q)) * NT_ + (i0 + 4 * p));

    float4 st = make_float4(0.f, 0.f, 0.f, 0.f);
    float4 sv = make_float4(0.f, 0.f, 0.f, 0.f);
#pragma unroll
    for (int h = 0; h < H_; ++h) {
        const float4 a = pt[h * hstride4];
        const float4 v = pv[h * hstride4];
        st.x += a.x; st.y += a.y; st.z += a.z; st.w += a.w;
        sv.x += v.x; sv.y += v.y; sv.z += v.z; sv.w += v.w;
    }

    // Stage P_v sums: shV[j - j0][i - i0]
    shV[q][4 * p + 0] = sv.x;
    shV[q][4 * p + 1] = sv.y;
    shV[q][4 * p + 2] = sv.z;
    shV[q][4 * p + 3] = sv.w;
    __syncthreads();

    // prod for (i = i0+q, j = j0+4p+c): needs shV[4p+c][q] (conflict-free).
    const float pr0 = st.x * shV[4 * p + 0][q];
    const float pr1 = st.y * shV[4 * p + 1][q];
    const float pr2 = st.z * shV[4 * p + 2][q];
    const float pr3 = st.w * shV[4 * p + 3][q];

    // Row sum over j: reduce the 8 threads (p = 0..7) sharing row q.
    float rs = (pr0 + pr1) + (pr2 + pr3);
    rs += __shfl_xor_sync(0xffffffffu, rs, 1);
    rs += __shfl_xor_sync(0xffffffffu, rs, 2);
    rs += __shfl_xor_sync(0xffffffffu, rs, 4);
    if (p == 0)
        atomicAdd(&g_tdiag[layer * (B_ * NT_) + b * NT_ + i0 + q], rs);

    // Column sums: stage prod tile, then read transposed.
    shP[q][4 * p + 0] = pr0;
    shP[q][4 * p + 1] = pr1;
    shP[q][4 * p + 2] = pr2;
    shP[q][4 * p + 3] = pr3;
    __syncthreads();

    // Thread handles column j = j0+q, rows i = 4p+c (conflict-free reads).
    float cs = shP[4 * p + 0][q] + shP[4 * p + 1][q]
             + shP[4 * p + 2][q] + shP[4 * p + 3][q];
    cs += __shfl_xor_sync(0xffffffffu, cs, 1);
    cs += __shfl_xor_sync(0xffffffffu, cs, 2);
    cs += __shfl_xor_sync(0xffffffffu, cs, 4);
    if (p == 0)
        atomicAdd(&g_vdiag[layer * (B_ * NV_) + b * NV_ + j0 + q], cs);
}

// Single-block reduction to the scalar loss. Re-zeroes the accumulators for
// the next call (each element is read and zeroed by the same thread).
__global__ __launch_bounds__(1024, 1)
void finalize_kernel(float* __restrict__ out) {
    __shared__ float red_t[32];
    __shared__ float red_v[32];
    const int tid = threadIdx.x;
    const float inv_h2 = 1.0f / (float)(H_ * H_);  // sums -> products of means

    float st = 0.0f, sv = 0.0f;
    for (int idx = tid; idx < 2 * B_ * NT_; idx += 1024) {
        float d = g_tdiag[idx] * inv_h2;
        g_tdiag[idx] = 0.0f;
        d = fminf(fmaxf(d, EPS_MIN), EPS_MAX);
        st -= logf(d);
    }
    for (int idx = tid; idx < 2 * B_ * NV_; idx += 1024) {
        float d = g_vdiag[idx] * inv_h2;
        g_vdiag[idx] = 0.0f;
        d = fminf(fmaxf(d, EPS_MIN), EPS_MAX);
        sv -= logf(d);
    }

#pragma unroll
    for (int o = 16; o > 0; o >>= 1) {
        st += __shfl_xor_sync(0xffffffffu, st, o);
        sv += __shfl_xor_sync(0xffffffffu, sv, o);
    }
    const int w = tid >> 5, l = tid & 31;
    if (l == 0) { red_t[w] = st; red_v[w] = sv; }
    __syncthreads();
    if (w == 0) {
        st = red_t[l];
        sv = red_v[l];
#pragma unroll
        for (int o = 16; o > 0; o >>= 1) {
            st += __shfl_xor_sync(0xffffffffu, st, o);
            sv += __shfl_xor_sync(0xffffffffu, sv, o);
        }
        if (l == 0) {
            // total = 0.25 * ((lt0+lt1) + (lv0+lv1))
            float loss = 0.25f * (st / (float)(B_ * NT_) + sv / (float)(B_ * NV_));
            out[0] = loss;
        }
    }
}

extern "C" void kernel_launch(void* const* d_in, const int* in_sizes, int n_in,
                              void* d_out, int out_size) {
    const float* at0 = (const float*)d_in[0];
    const float* av0 = (const float*)d_in[1];
    const float* at1 = (const float*)d_in[2];
    const float* av1 = (const float*)d_in[3];

    // Fused head-mean + diagonal row/col sums.
    // grid: x = NV/32 = 18 j-tiles, y = NT/32 = 16 i-tiles, z = layer*8 + b
    dim3 grid(NV_ / 32, NT_ / 32, 2 * B_);
    diag_kernel<<<grid, 256>>>(at0, av0, at1, av1);

    // Scalar finalize (also re-zeroes accumulators for the next call).
    finalize_kernel<<<1, 1024>>>((float*)d_out);
}

// round 3
// speedup vs baseline: 1.1722x; 1.0408x over previous
#include <cuda_runtime.h>

// Shapes fixed by the problem's setup_inputs().
#define B_  8
#define H_  16
#define NT_ 512
#define NV_ 576

#define EPS_MIN 1e-8f
#define EPS_MAX 1.0f

#define FIN_BLOCKS 32
#define FIN_THREADS 256

// Per-layer diagonal accumulators (atomic float adds).
// Zero-initialized at module load; finalize_kernel re-zeroes them after each
// use, so every kernel_launch call starts from zeros.
__device__ float g_tdiag[2 * B_ * NT_];   // 8192 floats
__device__ float g_vdiag[2 * B_ * NV_];   // 9216 floats

// Cross-block finalize scratch (zero-init; reset by the last block each call).
__device__ float        g_loss_t;
__device__ float        g_loss_v;
__device__ unsigned int g_ticket;

// One block (256 threads) = 32(i) x 32(j) tile for one (layer, b).
//   thread t: p = t & 7 (float4 slot), q = t >> 3 (row index 0..31)
//   attn_t: element (i = i0+q, j = j0+4p..+3)  -> float4 along j (contiguous)
//   attn_v: element (j = j0+q, i = i0+4p..+3)  -> float4 along i (contiguous)
// prod[i][j] = P_t_sum[i][j] * P_v_sum[j][i]; row sums -> g_tdiag,
// column sums -> g_vdiag.
__global__ __launch_bounds__(256)
void diag_kernel(const float* __restrict__ at0, const float* __restrict__ av0,
                 const float* __restrict__ at1, const float* __restrict__ av1) {
    __shared__ float shV[32][33];   // P_v sums, stride-33 -> conflict-free transpose
    __shared__ float shP[32][33];   // prod tile for column reduction

    const int t = threadIdx.x;
    const int p = t & 7;            // float4 slot within row
    const int q = t >> 3;           // row (i for attn_t, j for attn_v)

    const int z     = blockIdx.z;
    const int layer = z >> 3;
    const int b     = z & 7;
    const int i0    = blockIdx.y * 32;
    const int j0    = blockIdx.x * 32;

    const float* __restrict__ at = layer ? at1 : at0;
    const float* __restrict__ av = layer ? av1 : av0;

    // Base pointers at h = 0; head stride in float4 units.
    const size_t hstride4 = (size_t)NT_ * NV_ / 4;   // 73728
    const float4* __restrict__ pt = (const float4*)(
        at + (((size_t)b * H_) * NT_ + (i0 + q)) * NV_ + (j0 + 4 * p));
    const float4* __restrict__ pv = (const float4*)(
        av + (((size_t)b * H_) * NV_ + (j0 + q)) * NT_ + (i0 + 4 * p));

    float4 st = make_float4(0.f, 0.f, 0.f, 0.f);
    float4 sv = make_float4(0.f, 0.f, 0.f, 0.f);
#pragma unroll
    for (int h = 0; h < H_; ++h) {
        const float4 a = pt[h * hstride4];
        const float4 v = pv[h * hstride4];
        st.x += a.x; st.y += a.y; st.z += a.z; st.w += a.w;
        sv.x += v.x; sv.y += v.y; sv.z += v.z; sv.w += v.w;
    }

    // Stage P_v sums: shV[j - j0][i - i0]
    shV[q][4 * p + 0] = sv.x;
    shV[q][4 * p + 1] = sv.y;
    shV[q][4 * p + 2] = sv.z;
    shV[q][4 * p + 3] = sv.w;
    __syncthreads();

    // prod for (i = i0+q, j = j0+4p+c): needs shV[4p+c][q] (conflict-free).
    const float pr0 = st.x * shV[4 * p + 0][q];
    const float pr1 = st.y * shV[4 * p + 1][q];
    const float pr2 = st.z * shV[4 * p + 2][q];
    const float pr3 = st.w * shV[4 * p + 3][q];

    // Row sum over j: reduce the 8 threads (p = 0..7) sharing row q.
    float rs = (pr0 + pr1) + (pr2 + pr3);
    rs += __shfl_xor_sync(0xffffffffu, rs, 1);
    rs += __shfl_xor_sync(0xffffffffu, rs, 2);
    rs += __shfl_xor_sync(0xffffffffu, rs, 4);
    if (p == 0)
        atomicAdd(&g_tdiag[layer * (B_ * NT_) + b * NT_ + i0 + q], rs);

    // Column sums: stage prod tile, then read transposed.
    shP[q][4 * p + 0] = pr0;
    shP[q][4 * p + 1] = pr1;
    shP[q][4 * p + 2] = pr2;
    shP[q][4 * p + 3] = pr3;
    __syncthreads();

    // Thread handles column j = j0+q, rows i = 4p+c (conflict-free reads).
    float cs = shP[4 * p + 0][q] + shP[4 * p + 1][q]
             + shP[4 * p + 2][q] + shP[4 * p + 3][q];
    cs += __shfl_xor_sync(0xffffffffu, cs, 1);
    cs += __shfl_xor_sync(0xffffffffu, cs, 2);
    cs += __shfl_xor_sync(0xffffffffu, cs, 4);
    if (p == 0)
        atomicAdd(&g_vdiag[layer * (B_ * NV_) + b * NV_ + j0 + q], cs);
}

// Multi-block finalize: each block reduces a strided slice of the diag
// accumulators (re-zeroing them), atomicAdds partial -log sums into device
// scalars; the last block to finish combines and writes d_out, then resets
// the scratch for the next graph replay.
__global__ __launch_bounds__(FIN_THREADS)
void finalize_kernel(float* __restrict__ out) {
    __shared__ float red_t[FIN_THREADS / 32];
    __shared__ float red_v[FIN_THREADS / 32];
    __shared__ bool  is_last;

    const int tid  = threadIdx.x;
    const int gtid = blockIdx.x * FIN_THREADS + tid;
    const int nthr = FIN_BLOCKS * FIN_THREADS;
    const float inv_h2 = 1.0f / (float)(H_ * H_);

    float st = 0.0f, sv = 0.0f;
    for (int idx = gtid; idx < 2 * B_ * NT_; idx += nthr) {
        float d = g_tdiag[idx] * inv_h2;
        g_tdiag[idx] = 0.0f;
        d = fminf(fmaxf(d, EPS_MIN), EPS_MAX);
        st -= __logf(d);
    }
    for (int idx = gtid; idx < 2 * B_ * NV_; idx += nthr) {
        float d = g_vdiag[idx] * inv_h2;
        g_vdiag[idx] = 0.0f;
        d = fminf(fmaxf(d, EPS_MIN), EPS_MAX);
        sv -= __logf(d);
    }

#pragma unroll
    for (int o = 16; o > 0; o >>= 1) {
        st += __shfl_xor_sync(0xffffffffu, st, o);
        sv += __shfl_xor_sync(0xffffffffu, sv, o);
    }
    const int w = tid >> 5, l = tid & 31;
    if (l == 0) { red_t[w] = st; red_v[w] = sv; }
    __syncthreads();

    if (tid == 0) {
        float bt = 0.0f, bv = 0.0f;
#pragma unroll
        for (int k = 0; k < FIN_THREADS / 32; ++k) { bt += red_t[k]; bv += red_v[k]; }
        atomicAdd(&g_loss_t, bt);
        atomicAdd(&g_loss_v, bv);
        __threadfence();
        unsigned int ticket = atomicInc(&g_ticket, FIN_BLOCKS - 1);
        is_last = (ticket == FIN_BLOCKS - 1);
    }
    __syncthreads();

    if (is_last && tid == 0) {
        // All blocks' atomicAdds are visible (fence before each ticket inc).
        float lt = g_loss_t;
        float lv = g_loss_v;
        // total = 0.25 * ((lt0+lt1) + (lv0+lv1))
        out[0] = 0.25f * (lt / (float)(B_ * NT_) + lv / (float)(B_ * NV_));
        // Reset scratch for the next call / graph replay.
        g_loss_t = 0.0f;
        g_loss_v = 0.0f;
        // g_ticket wrapped to 0 by atomicInc's modulus.
    }
}

extern "C" void kernel_launch(void* const* d_in, const int* in_sizes, int n_in,
                              void* d_out, int out_size) {
    const float* at0 = (const float*)d_in[0];
    const float* av0 = (const float*)d_in[1];
    const float* at1 = (const float*)d_in[2];
    const float* av1 = (const float*)d_in[3];

    // Fused head-mean + diagonal row/col sums.
    // grid: x = NV/32 = 18 j-tiles, y = NT/32 = 16 i-tiles, z = layer*8 + b
    dim3 grid(NV_ / 32, NT_ / 32, 2 * B_);
    diag_kernel<<<grid, 256>>>(at0, av0, at1, av1);

    // Parallel finalize (also re-zeroes accumulators for the next call).
    finalize_kernel<<<FIN_BLOCKS, FIN_THREADS>>>((float*)d_out);
}